// round 1
// baseline (speedup 1.0000x reference)
#include <cuda_runtime.h>
#include <math.h>

// Problem constants (validated against in_sizes at launch)
#define NMAX 100000
#define EMAX 3200000
#define ND   128
#define INDIM 48

// ---------------- scratch (device globals; no allocation allowed) ----------------
__device__ float g_msg[(size_t)NMAX * ND];   // aggregated messages per layer
__device__ float g_deg[NMAX];
__device__ float g_dinv[NMAX];
__device__ int   g_rowptr[NMAX + 1];
__device__ int   g_fill[NMAX];               // used as: edge count, then scatter cursor
__device__ int   g_ecol[EMAX];               // CSR columns
__device__ float g_ew[EMAX];                 // CSR normalized weights
__device__ int   g_bsum[64];                 // scan block sums

// ---------------- small helpers ----------------
__device__ __forceinline__ void fma4(float4& d, float a, const float4& w) {
    d.x += a * w.x; d.y += a * w.y; d.z += a * w.z; d.w += a * w.w;
}

// ---------------- graph preprocessing kernels ----------------
__global__ void k_init(int n) {
    int i = blockIdx.x * blockDim.x + threadIdx.x;
    if (i < n) { g_deg[i] = 1.0f; g_fill[i] = 0; }   // 1.0f = self-loop value
}

__global__ void k_edge_deg(const int* __restrict__ row, const float* __restrict__ vals, int e) {
    int i = blockIdx.x * blockDim.x + threadIdx.x;
    if (i < e) {
        int r = row[i];
        atomicAdd(&g_deg[r], vals[i]);
        atomicAdd(&g_fill[r], 1);
    }
}

__global__ void k_dinv(int n) {
    int i = blockIdx.x * blockDim.x + threadIdx.x;
    if (i < n) {
        float d = fmaxf(g_deg[i], 1.0f);
        g_dinv[i] = 1.0f / sqrtf(d);
    }
}

// Exclusive scan over g_fill -> g_rowptr (3 phases). Tiles of 4096 per block.
__global__ void k_scanA(int n) {
    __shared__ int s[1024];
    int t = threadIdx.x;
    int base = blockIdx.x * 4096;
    int v[4]; int sum = 0;
#pragma unroll
    for (int k = 0; k < 4; k++) {
        int idx = base + t * 4 + k;
        v[k] = (idx < n) ? g_fill[idx] : 0;
        sum += v[k];
    }
    s[t] = sum;
    __syncthreads();
    for (int off = 1; off < 1024; off <<= 1) {
        int q = (t >= off) ? s[t - off] : 0;
        __syncthreads();
        s[t] += q;
        __syncthreads();
    }
    int excl = s[t] - sum;
    if (t == 1023) g_bsum[blockIdx.x] = s[1023];
    int run = excl;
#pragma unroll
    for (int k = 0; k < 4; k++) {
        int idx = base + t * 4 + k;
        if (idx < n) g_rowptr[idx] = run;
        run += v[k];
    }
}

__global__ void k_scanB(int nb) {
    if (threadIdx.x == 0 && blockIdx.x == 0) {
        int acc = 0;
        for (int i = 0; i < nb; i++) { int t = g_bsum[i]; g_bsum[i] = acc; acc += t; }
    }
}

__global__ void k_scanC(int n, int e) {
    int i = blockIdx.x * blockDim.x + threadIdx.x;
    if (i < n) {
        g_rowptr[i] += g_bsum[i >> 12];
        g_fill[i] = 0;                 // reuse as scatter cursor
    }
    if (i == 0) g_rowptr[n] = e;
}

__global__ void k_scatter(const int* __restrict__ row, const int* __restrict__ col,
                          const float* __restrict__ vals, int e) {
    int i = blockIdx.x * blockDim.x + threadIdx.x;
    if (i < e) {
        int r = row[i], c = col[i];
        int pos = g_rowptr[r] + atomicAdd(&g_fill[r], 1);
        g_ecol[pos] = c;
        g_ew[pos]   = vals[i] * g_dinv[r] * g_dinv[c];
    }
}

// ---------------- SpMM: warp-per-row gather (atomic-free) ----------------
__global__ void k_spmm(const float* __restrict__ x, int n) {
    int gt = blockIdx.x * blockDim.x + threadIdx.x;
    int w = gt >> 5;
    int lane = gt & 31;
    if (w >= n) return;
    const float4* x4 = (const float4*)x;
    float di = g_dinv[w];
    float s = di * di;                              // self-loop weight
    float4 v = x4[(size_t)w * 32 + lane];
    float4 acc = make_float4(s * v.x, s * v.y, s * v.z, s * v.w);
    int jb = g_rowptr[w], je = g_rowptr[w + 1];
    for (int j = jb; j < je; j++) {
        int c = g_ecol[j];
        float wt = g_ew[j];
        float4 u = x4[(size_t)c * 32 + lane];
        acc.x += wt * u.x; acc.y += wt * u.y; acc.z += wt * u.z; acc.w += wt * u.w;
    }
    ((float4*)g_msg)[(size_t)w * 32 + lane] = acc;
}

// ---------------- GEMM + bias + ReLU (+ residual) ----------------
// Out[i,:] (RES ? += : =) relu(A[i,:K] @ W[K,128] + b)
// 64 rows/block, 256 threads: 16 col-groups (8 cols each) x 16 row-groups (4 rows each)
template<int K, bool RES, bool A_IS_MSG>
__global__ void k_gemm(const float* __restrict__ Ain, const float* __restrict__ W,
                       const float* __restrict__ b, float* __restrict__ X, int n) {
    const int ASTR = K + 4;
    __shared__ float As[64 * (K + 4)];
    const float* A = A_IS_MSG ? (const float*)g_msg : Ain;
    int tid = threadIdx.x;
    int rowBase = blockIdx.x * 64;

    // stage A tile into smem (float4)
    const float4* A4 = (const float4*)A;
    for (int idx = tid; idx < 64 * (K / 4); idx += 256) {
        int lr = idx / (K / 4);
        int kk = idx - lr * (K / 4);
        int gr = rowBase + lr;
        float4 v = make_float4(0.f, 0.f, 0.f, 0.f);
        if (gr < n) v = A4[(size_t)gr * (K / 4) + kk];
        *(float4*)&As[lr * ASTR + kk * 4] = v;
    }
    __syncthreads();

    int tc = tid & 15;          // col group: cols [tc*8, tc*8+8)
    int tr = tid >> 4;          // row group: rows [tr*4, tr*4+4)

    const float4* W4 = (const float4*)W;
    float4 acc[4][2];
#pragma unroll
    for (int r = 0; r < 4; r++) {
        acc[r][0] = make_float4(0.f, 0.f, 0.f, 0.f);
        acc[r][1] = make_float4(0.f, 0.f, 0.f, 0.f);
    }

#pragma unroll 8
    for (int k = 0; k < K; k++) {
        float a0 = As[(tr * 4 + 0) * ASTR + k];
        float a1 = As[(tr * 4 + 1) * ASTR + k];
        float a2 = As[(tr * 4 + 2) * ASTR + k];
        float a3 = As[(tr * 4 + 3) * ASTR + k];
        float4 w0 = __ldg(&W4[k * 32 + tc * 2 + 0]);
        float4 w1 = __ldg(&W4[k * 32 + tc * 2 + 1]);
        fma4(acc[0][0], a0, w0); fma4(acc[0][1], a0, w1);
        fma4(acc[1][0], a1, w0); fma4(acc[1][1], a1, w1);
        fma4(acc[2][0], a2, w0); fma4(acc[2][1], a2, w1);
        fma4(acc[3][0], a3, w0); fma4(acc[3][1], a3, w1);
    }

    float4 bb0 = __ldg(&((const float4*)b)[tc * 2 + 0]);
    float4 bb1 = __ldg(&((const float4*)b)[tc * 2 + 1]);
    float4* X4 = (float4*)X;
#pragma unroll
    for (int r = 0; r < 4; r++) {
        int gr = rowBase + tr * 4 + r;
        if (gr < n) {
            float4 o0, o1;
            o0.x = fmaxf(acc[r][0].x + bb0.x, 0.f);
            o0.y = fmaxf(acc[r][0].y + bb0.y, 0.f);
            o0.z = fmaxf(acc[r][0].z + bb0.z, 0.f);
            o0.w = fmaxf(acc[r][0].w + bb0.w, 0.f);
            o1.x = fmaxf(acc[r][1].x + bb1.x, 0.f);
            o1.y = fmaxf(acc[r][1].y + bb1.y, 0.f);
            o1.z = fmaxf(acc[r][1].z + bb1.z, 0.f);
            o1.w = fmaxf(acc[r][1].w + bb1.w, 0.f);
            size_t base = (size_t)gr * 32 + tc * 2;
            if (RES) {
                float4 x0 = X4[base + 0];
                float4 x1 = X4[base + 1];
                o0.x += x0.x; o0.y += x0.y; o0.z += x0.z; o0.w += x0.w;
                o1.x += x1.x; o1.y += x1.y; o1.z += x1.z; o1.w += x1.w;
            }
            X4[base + 0] = o0;
            X4[base + 1] = o1;
        }
    }
}

// ---------------- launch ----------------
extern "C" void kernel_launch(void* const* d_in, const int* in_sizes, int n_in,
                              void* d_out, int out_size) {
    const float* nf    = (const float*)d_in[0];   // [N,48]
    const int*   erow  = (const int*)d_in[1];     // [E]
    const int*   ecol  = (const int*)d_in[2];     // [E]
    const float* evals = (const float*)d_in[3];   // [E]
    const float* Win   = (const float*)d_in[4];   // [48,128]
    const float* bin   = (const float*)d_in[5];   // [128]
    const float* Wc    = (const float*)d_in[6];   // [L,128,128]
    const float* bc    = (const float*)d_in[7];   // [L,128]

    int N = in_sizes[0] / INDIM;
    int E = in_sizes[1];
    int L = in_sizes[6] / (ND * ND);
    if (N > NMAX) N = NMAX;
    if (E > EMAX) E = EMAX;

    float* x = (float*)d_out;

    // graph preprocessing (CSR + normalization), rebuilt every call
    k_init<<<(N + 255) / 256, 256>>>(N);
    k_edge_deg<<<(E + 255) / 256, 256>>>(erow, evals, E);
    k_dinv<<<(N + 255) / 256, 256>>>(N);
    int nb = (N + 4095) / 4096;
    k_scanA<<<nb, 1024>>>(N);
    k_scanB<<<1, 32>>>(nb);
    k_scanC<<<(N + 255) / 256, 256>>>(N, E);
    k_scatter<<<(E + 255) / 256, 256>>>(erow, ecol, evals, E);

    // input projection: x = relu(nf @ Win + bin)
    k_gemm<INDIM, false, false><<<(N + 63) / 64, 256>>>(nf, Win, bin, x, N);

    // layers: msg = A_hat_norm @ x ; x += relu(msg @ Wc[l] + bc[l])
    int spmm_blocks = (N * 32 + 255) / 256;
    for (int l = 0; l < L; l++) {
        k_spmm<<<spmm_blocks, 256>>>(x, N);
        k_gemm<ND, true, true><<<(N + 63) / 64, 256>>>(nullptr, Wc + (size_t)l * ND * ND,
                                                       bc + (size_t)l * ND, x, N);
    }
}

// round 2
// speedup vs baseline: 1.1271x; 1.1271x over previous
#include <cuda_runtime.h>
#include <cuda_fp16.h>
#include <math.h>

// Problem constants (validated against in_sizes at launch)
#define NMAX 100000
#define EMAX 3200000
#define ND   128
#define INDIM 48

// ---------------- scratch (device globals; no allocation allowed) ----------------
__device__ __align__(16) __half g_y[(size_t)NMAX * ND];  // x @ W, fp16, gathered by SpMM
__device__ float g_deg[NMAX];
__device__ float g_dinv[NMAX];
__device__ int   g_rowptr[NMAX + 1];
__device__ int   g_fill[NMAX];               // used as: edge count, then scatter cursor
__device__ int   g_ecol[EMAX];               // CSR columns
__device__ float g_ew[EMAX];                 // CSR normalized weights
__device__ int   g_bsum[64];                 // scan block sums

// ---------------- small helpers ----------------
__device__ __forceinline__ void fma4(float4& d, float a, const float4& w) {
    d.x += a * w.x; d.y += a * w.y; d.z += a * w.z; d.w += a * w.w;
}
__device__ __forceinline__ float4 h4_to_f4(uint2 u) {
    __half2 a = *(__half2*)&u.x;
    __half2 b = *(__half2*)&u.y;
    float2 fa = __half22float2(a);
    float2 fb = __half22float2(b);
    return make_float4(fa.x, fa.y, fb.x, fb.y);
}

// ---------------- graph preprocessing kernels ----------------
__global__ void k_init(int n) {
    int i = blockIdx.x * blockDim.x + threadIdx.x;
    if (i < n) { g_deg[i] = 1.0f; g_fill[i] = 0; }   // 1.0f = self-loop value
}

__global__ void k_edge_deg(const int* __restrict__ row, const float* __restrict__ vals, int e) {
    int i = blockIdx.x * blockDim.x + threadIdx.x;
    if (i < e) {
        int r = row[i];
        atomicAdd(&g_deg[r], vals[i]);
        atomicAdd(&g_fill[r], 1);
    }
}

__global__ void k_dinv(int n) {
    int i = blockIdx.x * blockDim.x + threadIdx.x;
    if (i < n) {
        float d = fmaxf(g_deg[i], 1.0f);
        g_dinv[i] = rsqrtf(d);
    }
}

// Exclusive scan over g_fill -> g_rowptr (3 phases). Tiles of 4096 per block.
__global__ void k_scanA(int n) {
    __shared__ int s[1024];
    int t = threadIdx.x;
    int base = blockIdx.x * 4096;
    int v[4]; int sum = 0;
#pragma unroll
    for (int k = 0; k < 4; k++) {
        int idx = base + t * 4 + k;
        v[k] = (idx < n) ? g_fill[idx] : 0;
        sum += v[k];
    }
    s[t] = sum;
    __syncthreads();
    for (int off = 1; off < 1024; off <<= 1) {
        int q = (t >= off) ? s[t - off] : 0;
        __syncthreads();
        s[t] += q;
        __syncthreads();
    }
    int excl = s[t] - sum;
    if (t == 1023) g_bsum[blockIdx.x] = s[1023];
    int run = excl;
#pragma unroll
    for (int k = 0; k < 4; k++) {
        int idx = base + t * 4 + k;
        if (idx < n) g_rowptr[idx] = run;
        run += v[k];
    }
}

__global__ void k_scanB(int nb) {
    if (threadIdx.x == 0 && blockIdx.x == 0) {
        int acc = 0;
        for (int i = 0; i < nb; i++) { int t = g_bsum[i]; g_bsum[i] = acc; acc += t; }
    }
}

__global__ void k_scanC(int n, int e) {
    int i = blockIdx.x * blockDim.x + threadIdx.x;
    if (i < n) {
        g_rowptr[i] += g_bsum[i >> 12];
        g_fill[i] = 0;                 // reuse as scatter cursor
    }
    if (i == 0) g_rowptr[n] = e;
}

__global__ void k_scatter(const int* __restrict__ row, const int* __restrict__ col,
                          const float* __restrict__ vals, int e) {
    int i = blockIdx.x * blockDim.x + threadIdx.x;
    if (i < e) {
        int r = row[i], c = col[i];
        int pos = g_rowptr[r] + atomicAdd(&g_fill[r], 1);
        g_ecol[pos] = c;
        g_ew[pos]   = vals[i] * g_dinv[r] * g_dinv[c];
    }
}

// ---------------- SpMM (fp16 gather) + bias + ReLU + residual, fused ----------------
// x[w,:] += relu( sum_j ew[j]*y[col[j],:] + dinv[w]^2*y[w,:] + b )
__global__ void k_spmm_fused(float* __restrict__ x, const float* __restrict__ b, int n) {
    int gt = blockIdx.x * blockDim.x + threadIdx.x;
    int w = gt >> 5;
    int lane = gt & 31;
    if (w >= n) return;
    const uint2* y2 = (const uint2*)g_y;        // 4 halfs per lane
    float di = g_dinv[w];
    float s = di * di;                          // self-loop weight
    float4 v = h4_to_f4(y2[(size_t)w * 32 + lane]);
    float4 acc = make_float4(s * v.x, s * v.y, s * v.z, s * v.w);
    int jb = g_rowptr[w], je = g_rowptr[w + 1];
    int j = jb;
    for (; j + 4 <= je; j += 4) {
        int   c0 = g_ecol[j],   c1 = g_ecol[j+1], c2 = g_ecol[j+2], c3 = g_ecol[j+3];
        float w0 = g_ew[j],     w1 = g_ew[j+1],   w2 = g_ew[j+2],   w3 = g_ew[j+3];
        uint2 u0 = y2[(size_t)c0 * 32 + lane];
        uint2 u1 = y2[(size_t)c1 * 32 + lane];
        uint2 u2 = y2[(size_t)c2 * 32 + lane];
        uint2 u3 = y2[(size_t)c3 * 32 + lane];
        fma4(acc, w0, h4_to_f4(u0));
        fma4(acc, w1, h4_to_f4(u1));
        fma4(acc, w2, h4_to_f4(u2));
        fma4(acc, w3, h4_to_f4(u3));
    }
    for (; j < je; j++) {
        int c = g_ecol[j];
        float wt = g_ew[j];
        fma4(acc, wt, h4_to_f4(y2[(size_t)c * 32 + lane]));
    }
    float4 bb = __ldg(&((const float4*)b)[lane]);
    float4* x4 = (float4*)x;
    float4 xv = x4[(size_t)w * 32 + lane];
    xv.x += fmaxf(acc.x + bb.x, 0.f);
    xv.y += fmaxf(acc.y + bb.y, 0.f);
    xv.z += fmaxf(acc.z + bb.z, 0.f);
    xv.w += fmaxf(acc.w + bb.w, 0.f);
    x4[(size_t)w * 32 + lane] = xv;
}

// ---------------- GEMM: Out[i,:] = A[i,:K] @ W[K,128]  (two epilogues) ----------------
// MODE 0: out = relu(acc + b) -> float* (input projection)
// MODE 1: out = acc           -> half*  (layer pre-aggregation y = x @ W)
// 64 rows/block, 256 threads: 16 col-groups (8 cols each) x 16 row-groups (4 rows each)
template<int K, int MODE>
__global__ void k_gemm(const float* __restrict__ A, const float* __restrict__ W,
                       const float* __restrict__ b, float* __restrict__ Xout, int n) {
    const int ASTR = K + 4;
    __shared__ float As[64 * (K + 4)];
    int tid = threadIdx.x;
    int rowBase = blockIdx.x * 64;

    // stage A tile into smem (float4)
    const float4* A4 = (const float4*)A;
    for (int idx = tid; idx < 64 * (K / 4); idx += 256) {
        int lr = idx / (K / 4);
        int kk = idx - lr * (K / 4);
        int gr = rowBase + lr;
        float4 v = make_float4(0.f, 0.f, 0.f, 0.f);
        if (gr < n) v = A4[(size_t)gr * (K / 4) + kk];
        *(float4*)&As[lr * ASTR + kk * 4] = v;
    }
    __syncthreads();

    int tc = tid & 15;          // col group: cols [tc*8, tc*8+8)
    int tr = tid >> 4;          // row group: rows [tr*4, tr*4+4)

    const float4* W4 = (const float4*)W;
    float4 acc[4][2];
#pragma unroll
    for (int r = 0; r < 4; r++) {
        acc[r][0] = make_float4(0.f, 0.f, 0.f, 0.f);
        acc[r][1] = make_float4(0.f, 0.f, 0.f, 0.f);
    }

#pragma unroll 8
    for (int k = 0; k < K; k++) {
        float a0 = As[(tr * 4 + 0) * ASTR + k];
        float a1 = As[(tr * 4 + 1) * ASTR + k];
        float a2 = As[(tr * 4 + 2) * ASTR + k];
        float a3 = As[(tr * 4 + 3) * ASTR + k];
        float4 w0 = __ldg(&W4[k * 32 + tc * 2 + 0]);
        float4 w1 = __ldg(&W4[k * 32 + tc * 2 + 1]);
        fma4(acc[0][0], a0, w0); fma4(acc[0][1], a0, w1);
        fma4(acc[1][0], a1, w0); fma4(acc[1][1], a1, w1);
        fma4(acc[2][0], a2, w0); fma4(acc[2][1], a2, w1);
        fma4(acc[3][0], a3, w0); fma4(acc[3][1], a3, w1);
    }

    if (MODE == 0) {
        float4 bb0 = __ldg(&((const float4*)b)[tc * 2 + 0]);
        float4 bb1 = __ldg(&((const float4*)b)[tc * 2 + 1]);
        float4* X4 = (float4*)Xout;
#pragma unroll
        for (int r = 0; r < 4; r++) {
            int gr = rowBase + tr * 4 + r;
            if (gr < n) {
                float4 o0, o1;
                o0.x = fmaxf(acc[r][0].x + bb0.x, 0.f);
                o0.y = fmaxf(acc[r][0].y + bb0.y, 0.f);
                o0.z = fmaxf(acc[r][0].z + bb0.z, 0.f);
                o0.w = fmaxf(acc[r][0].w + bb0.w, 0.f);
                o1.x = fmaxf(acc[r][1].x + bb1.x, 0.f);
                o1.y = fmaxf(acc[r][1].y + bb1.y, 0.f);
                o1.z = fmaxf(acc[r][1].z + bb1.z, 0.f);
                o1.w = fmaxf(acc[r][1].w + bb1.w, 0.f);
                size_t base = (size_t)gr * 32 + tc * 2;
                X4[base + 0] = o0;
                X4[base + 1] = o1;
            }
        }
    } else {
        // pack 8 fp32 -> 8 fp16 -> one uint4 store per row
        uint4* Y4 = (uint4*)g_y;           // row = 16 uint4 (128 halfs)
#pragma unroll
        for (int r = 0; r < 4; r++) {
            int gr = rowBase + tr * 4 + r;
            if (gr < n) {
                __half2 h0 = __floats2half2_rn(acc[r][0].x, acc[r][0].y);
                __half2 h1 = __floats2half2_rn(acc[r][0].z, acc[r][0].w);
                __half2 h2 = __floats2half2_rn(acc[r][1].x, acc[r][1].y);
                __half2 h3 = __floats2half2_rn(acc[r][1].z, acc[r][1].w);
                uint4 p;
                p.x = *(unsigned*)&h0; p.y = *(unsigned*)&h1;
                p.z = *(unsigned*)&h2; p.w = *(unsigned*)&h3;
                Y4[(size_t)gr * 16 + tc] = p;
            }
        }
    }
}

// ---------------- launch ----------------
extern "C" void kernel_launch(void* const* d_in, const int* in_sizes, int n_in,
                              void* d_out, int out_size) {
    const float* nf    = (const float*)d_in[0];   // [N,48]
    const int*   erow  = (const int*)d_in[1];     // [E]
    const int*   ecol  = (const int*)d_in[2];     // [E]
    const float* evals = (const float*)d_in[3];   // [E]
    const float* Win   = (const float*)d_in[4];   // [48,128]
    const float* bin   = (const float*)d_in[5];   // [128]
    const float* Wc    = (const float*)d_in[6];   // [L,128,128]
    const float* bc    = (const float*)d_in[7];   // [L,128]

    int N = in_sizes[0] / INDIM;
    int E = in_sizes[1];
    int L = in_sizes[6] / (ND * ND);
    if (N > NMAX) N = NMAX;
    if (E > EMAX) E = EMAX;

    float* x = (float*)d_out;

    // graph preprocessing (CSR + normalization), rebuilt every call
    k_init<<<(N + 255) / 256, 256>>>(N);
    k_edge_deg<<<(E + 255) / 256, 256>>>(erow, evals, E);
    k_dinv<<<(N + 255) / 256, 256>>>(N);
    int nb = (N + 4095) / 4096;
    k_scanA<<<nb, 1024>>>(N);
    k_scanB<<<1, 32>>>(nb);
    k_scanC<<<(N + 255) / 256, 256>>>(N, E);
    k_scatter<<<(E + 255) / 256, 256>>>(erow, ecol, evals, E);

    // input projection: x = relu(nf @ Win + bin)
    k_gemm<INDIM, 0><<<(N + 63) / 64, 256>>>(nf, Win, bin, x, N);

    // layers (commuted): y = x @ Wc[l] (fp16) ; x += relu(A_hat_norm @ y + bc[l])
    int spmm_blocks = (N * 32 + 255) / 256;
    for (int l = 0; l < L; l++) {
        k_gemm<ND, 1><<<(N + 63) / 64, 256>>>(x, Wc + (size_t)l * ND * ND, nullptr, nullptr, N);
        k_spmm_fused<<<spmm_blocks, 256>>>(x, bc + (size_t)l * ND, N);
    }
}

// round 5
// speedup vs baseline: 1.8890x; 1.6760x over previous
#include <cuda_runtime.h>
#include <cuda_fp16.h>
#include <math.h>

// Problem constants (validated against in_sizes at launch)
#define NMAX 100000
#define NPAD 100128           // NMAX rounded up past 128-row tile
#define EMAX 3200000
#define ND   128
#define INDIM 48

// ---------------- scratch (device globals; no allocation allowed) ----------------
__device__ __align__(16) __half g_y[(size_t)NPAD * ND];    // x @ W (fp16), gathered by SpMM
__device__ __align__(16) __half g_xh[(size_t)NPAD * ND];   // fp16 copy of x (GEMM A operand)
__device__ __align__(16) __half g_nfh[(size_t)NPAD * INDIM]; // fp16 copy of node_features
__device__ __align__(16) uint2  g_wpack[1536 + 3 * 4096];  // W in mma-B-fragment order
__device__ float g_deg[NMAX];
__device__ float g_dinv[NMAX];
__device__ int   g_rowptr[NMAX + 1];
__device__ int   g_fill[NMAX];
__device__ int   g_ecol[EMAX];
__device__ float g_ew[EMAX];
__device__ int   g_bsum[64];

// ---------------- small helpers ----------------
__device__ __forceinline__ void fma4(float4& d, float a, const float4& w) {
    d.x += a * w.x; d.y += a * w.y; d.z += a * w.z; d.w += a * w.w;
}
__device__ __forceinline__ float4 h4_to_f4(uint2 u) {
    __half2 a = *(__half2*)&u.x;
    __half2 b = *(__half2*)&u.y;
    float2 fa = __half22float2(a);
    float2 fb = __half22float2(b);
    return make_float4(fa.x, fa.y, fb.x, fb.y);
}
__device__ __forceinline__ unsigned pack_h2(float a, float b) {
    __half2 h = __floats2half2_rn(a, b);
    return *(unsigned*)&h;
}
__device__ __forceinline__ void mma16816(float4& c, unsigned a0, unsigned a1, unsigned a2,
                                         unsigned a3, unsigned b0, unsigned b1) {
    asm volatile(
        "mma.sync.aligned.m16n8k16.row.col.f32.f16.f16.f32 "
        "{%0,%1,%2,%3}, {%4,%5,%6,%7}, {%8,%9}, {%0,%1,%2,%3};\n"
        : "+f"(c.x), "+f"(c.y), "+f"(c.z), "+f"(c.w)
        : "r"(a0), "r"(a1), "r"(a2), "r"(a3), "r"(b0), "r"(b1));
}

// ---------------- graph preprocessing ----------------
__global__ void k_init(int n) {
    int i = blockIdx.x * blockDim.x + threadIdx.x;
    if (i < n) { g_deg[i] = 1.0f; g_fill[i] = 0; }   // 1.0f = self-loop value
}

__global__ void k_edge_deg(const int* __restrict__ row, const float* __restrict__ vals, int e) {
    int i = blockIdx.x * blockDim.x + threadIdx.x;
    if (i < e) {
        int r = row[i];
        atomicAdd(&g_deg[r], vals[i]);
        atomicAdd(&g_fill[r], 1);
    }
}

__global__ void k_dinv(int n) {
    int i = blockIdx.x * blockDim.x + threadIdx.x;
    if (i < n) g_dinv[i] = rsqrtf(fmaxf(g_deg[i], 1.0f));
}

__global__ void k_scanA(int n) {
    __shared__ int s[1024];
    int t = threadIdx.x;
    int base = blockIdx.x * 4096;
    int v[4]; int sum = 0;
#pragma unroll
    for (int k = 0; k < 4; k++) {
        int idx = base + t * 4 + k;
        v[k] = (idx < n) ? g_fill[idx] : 0;
        sum += v[k];
    }
    s[t] = sum;
    __syncthreads();
    for (int off = 1; off < 1024; off <<= 1) {
        int q = (t >= off) ? s[t - off] : 0;
        __syncthreads();
        s[t] += q;
        __syncthreads();
    }
    int excl = s[t] - sum;
    if (t == 1023) g_bsum[blockIdx.x] = s[1023];
    int run = excl;
#pragma unroll
    for (int k = 0; k < 4; k++) {
        int idx = base + t * 4 + k;
        if (idx < n) g_rowptr[idx] = run;
        run += v[k];
    }
}

__global__ void k_scanB(int nb) {
    if (threadIdx.x == 0 && blockIdx.x == 0) {
        int acc = 0;
        for (int i = 0; i < nb; i++) { int t = g_bsum[i]; g_bsum[i] = acc; acc += t; }
    }
}

__global__ void k_scanC(int n, int e) {
    int i = blockIdx.x * blockDim.x + threadIdx.x;
    if (i < n) {
        g_rowptr[i] += g_bsum[i >> 12];
        g_fill[i] = 0;
    }
    if (i == 0) g_rowptr[n] = e;
}

__global__ void k_scatter(const int* __restrict__ row, const int* __restrict__ col,
                          const float* __restrict__ vals, int e) {
    int i = blockIdx.x * blockDim.x + threadIdx.x;
    if (i < e) {
        int r = row[i], c = col[i];
        int pos = g_rowptr[r] + atomicAdd(&g_fill[r], 1);
        g_ecol[pos] = c;
        g_ew[pos]   = vals[i] * g_dinv[r] * g_dinv[c];
    }
}

// ---------------- weight repack (fp32 -> fp16 mma B-fragment order) ----------------
// Slot 0: Win (KC=3) at offset 0 (1536 uint2). Slot l+1: Wc[l] (KC=8) at 1536 + l*4096.
// Fragment: index = kc*512 + nt*32 + lane; n = nt*8 + lane/4, k0 = kc*16 + (lane%4)*2
//   .x = half2(W[k0][n],   W[k0+1][n])
//   .y = half2(W[k0+8][n], W[k0+9][n])
__global__ void k_pack_w(const float* __restrict__ Win, const float* __restrict__ Wc, int L) {
    int t = blockIdx.x * blockDim.x + threadIdx.x;
    int total = 1536 + L * 4096;
    if (t >= total) return;
    const float* W;
    int idx;
    if (t < 1536) { W = Win; idx = t; }
    else {
        int l = (t - 1536) >> 12;
        idx = (t - 1536) & 4095;
        W = Wc + (size_t)l * ND * ND;
    }
    int kc   = idx >> 9;
    int rest = idx & 511;
    int nt   = rest >> 5;
    int lane = rest & 31;
    int n  = nt * 8 + (lane >> 2);
    int k0 = kc * 16 + (lane & 3) * 2;
    uint2 p;
    p.x = pack_h2(W[(size_t)k0 * ND + n],       W[(size_t)(k0 + 1) * ND + n]);
    p.y = pack_h2(W[(size_t)(k0 + 8) * ND + n], W[(size_t)(k0 + 9) * ND + n]);
    g_wpack[t] = p;
}

// ---------------- node_features fp32 -> fp16 ----------------
__global__ void k_cvt_nf(const float* __restrict__ nf, int cnt4) {
    int i = blockIdx.x * blockDim.x + threadIdx.x;
    if (i >= cnt4) return;
    float4 v = ((const float4*)nf)[i];
    uint2 p;
    p.x = pack_h2(v.x, v.y);
    p.y = pack_h2(v.z, v.w);
    ((uint2*)g_nfh)[i] = p;
}

// ---------------- tensor-core GEMM ----------------
// Block: 64 rows x 128 cols, 256 threads (8 warps).
// Warp w: row-group rg = w/2 (rows [rg*16, rg*16+16)), col-half h = w%2 (cols [h*64, h*64+64)).
// Per-warp accumulator: 8 x float4 (16x64 tile) -> register-resident, no spill.
// A selected by ASEL (0: g_nfh, 1: g_xh) inside device code. B: g_wpack + wofs.
// MODE 0: out = relu(acc + bias) -> Xout fp32 AND g_xh fp16 (input projection)
// MODE 1: out = acc -> g_y fp16 (layer pre-aggregation)
template<int KC, int MODE, int ASEL>
__global__ void __launch_bounds__(256)
k_mma(int wofs, const float* __restrict__ bias, float* __restrict__ Xout, int n) {
    const int AS = KC * 16;
    const __half* A = (ASEL == 0) ? g_nfh : g_xh;
    int tid = threadIdx.x;
    int warp = tid >> 5, lane = tid & 31;
    int rg = warp >> 1, h = warp & 1;
    int g = lane >> 2, tq = lane & 3;
    int row0 = blockIdx.x * 64 + rg * 16;

    float4 acc[8];
#pragma unroll
    for (int nt = 0; nt < 8; nt++) acc[nt] = make_float4(0.f, 0.f, 0.f, 0.f);

    const __half* ar0 = A + (size_t)(row0 + g) * AS;
    const __half* ar8 = A + (size_t)(row0 + g + 8) * AS;
    const uint2* wp = g_wpack + wofs + h * 256 + lane;

#pragma unroll
    for (int kc = 0; kc < KC; kc++) {
        int k0 = kc * 16 + tq * 2;
        unsigned a0 = *(const unsigned*)(ar0 + k0);
        unsigned a1 = *(const unsigned*)(ar8 + k0);
        unsigned a2 = *(const unsigned*)(ar0 + k0 + 8);
        unsigned a3 = *(const unsigned*)(ar8 + k0 + 8);
        const uint2* w = wp + kc * 512;
#pragma unroll
        for (int nt = 0; nt < 8; nt++) {
            uint2 b = __ldg(&w[nt * 32]);
            mma16816(acc[nt], a0, a1, a2, a3, b.x, b.y);
        }
    }

    int r0 = row0 + g;
    int r1 = row0 + g + 8;
    bool ok0 = r0 < n, ok1 = r1 < n;
    int colb = h * 64 + tq * 2;          // base column for this thread's c0/c1

    if (MODE == 1) {
        __half* y0 = g_y + (size_t)r0 * ND + colb;
        __half* y1 = g_y + (size_t)r1 * ND + colb;
#pragma unroll
        for (int nt = 0; nt < 8; nt++) {
            unsigned h01 = pack_h2(acc[nt].x, acc[nt].y);
            unsigned h23 = pack_h2(acc[nt].z, acc[nt].w);
            if (ok0) *(unsigned*)(y0 + nt * 8) = h01;
            if (ok1) *(unsigned*)(y1 + nt * 8) = h23;
        }
    } else {
        __half* xh0 = g_xh + (size_t)r0 * ND + colb;
        __half* xh1 = g_xh + (size_t)r1 * ND + colb;
        float*  xo0 = Xout + (size_t)r0 * ND + colb;
        float*  xo1 = Xout + (size_t)r1 * ND + colb;
#pragma unroll
        for (int nt = 0; nt < 8; nt++) {
            float2 bb = __ldg(&((const float2*)bias)[h * 32 + nt * 4 + tq]);
            float v0 = fmaxf(acc[nt].x + bb.x, 0.f);
            float v1 = fmaxf(acc[nt].y + bb.y, 0.f);
            float v2 = fmaxf(acc[nt].z + bb.x, 0.f);
            float v3 = fmaxf(acc[nt].w + bb.y, 0.f);
            if (ok0) {
                *(float2*)(xo0 + nt * 8) = make_float2(v0, v1);
                *(unsigned*)(xh0 + nt * 8) = pack_h2(v0, v1);
            }
            if (ok1) {
                *(float2*)(xo1 + nt * 8) = make_float2(v2, v3);
                *(unsigned*)(xh1 + nt * 8) = pack_h2(v2, v3);
            }
        }
    }
}

// ---------------- SpMM (fp16 gather) + bias + ReLU + residual, fused ----------------
// x[w,:] += relu( sum_j ew[j]*y[col[j],:] + dinv[w]^2*y[w,:] + b ); also refresh g_xh
__global__ void k_spmm_fused(float* __restrict__ x, const float* __restrict__ b, int n) {
    int gt = blockIdx.x * blockDim.x + threadIdx.x;
    int w = gt >> 5;
    int lane = gt & 31;
    if (w >= n) return;
    const uint2* y2 = (const uint2*)g_y;        // 4 halfs per lane
    float di = g_dinv[w];
    float s = di * di;                          // self-loop weight
    float4 v = h4_to_f4(y2[(size_t)w * 32 + lane]);
    float4 acc = make_float4(s * v.x, s * v.y, s * v.z, s * v.w);
    int jb = g_rowptr[w], je = g_rowptr[w + 1];
    int j = jb;
    for (; j + 4 <= je; j += 4) {
        int   c0 = g_ecol[j],   c1 = g_ecol[j+1], c2 = g_ecol[j+2], c3 = g_ecol[j+3];
        float w0 = g_ew[j],     w1 = g_ew[j+1],   w2 = g_ew[j+2],   w3 = g_ew[j+3];
        uint2 u0 = y2[(size_t)c0 * 32 + lane];
        uint2 u1 = y2[(size_t)c1 * 32 + lane];
        uint2 u2 = y2[(size_t)c2 * 32 + lane];
        uint2 u3 = y2[(size_t)c3 * 32 + lane];
        fma4(acc, w0, h4_to_f4(u0));
        fma4(acc, w1, h4_to_f4(u1));
        fma4(acc, w2, h4_to_f4(u2));
        fma4(acc, w3, h4_to_f4(u3));
    }
    for (; j < je; j++) {
        fma4(acc, g_ew[j], h4_to_f4(y2[(size_t)g_ecol[j] * 32 + lane]));
    }
    float4 bb = __ldg(&((const float4*)b)[lane]);
    float4* x4 = (float4*)x;
    float4 xv = x4[(size_t)w * 32 + lane];
    xv.x += fmaxf(acc.x + bb.x, 0.f);
    xv.y += fmaxf(acc.y + bb.y, 0.f);
    xv.z += fmaxf(acc.z + bb.z, 0.f);
    xv.w += fmaxf(acc.w + bb.w, 0.f);
    x4[(size_t)w * 32 + lane] = xv;
    uint2 p;
    p.x = pack_h2(xv.x, xv.y);
    p.y = pack_h2(xv.z, xv.w);
    ((uint2*)g_xh)[(size_t)w * 32 + lane] = p;
}

// ---------------- launch ----------------
extern "C" void kernel_launch(void* const* d_in, const int* in_sizes, int n_in,
                              void* d_out, int out_size) {
    const float* nf    = (const float*)d_in[0];   // [N,48]
    const int*   erow  = (const int*)d_in[1];     // [E]
    const int*   ecol  = (const int*)d_in[2];     // [E]
    const float* evals = (const float*)d_in[3];   // [E]
    const float* Win   = (const float*)d_in[4];   // [48,128]
    const float* bin   = (const float*)d_in[5];   // [128]
    const float* Wc    = (const float*)d_in[6];   // [L,128,128]
    const float* bc    = (const float*)d_in[7];   // [L,128]

    int N = in_sizes[0] / INDIM;
    int E = in_sizes[1];
    int L = in_sizes[6] / (ND * ND);
    if (N > NMAX) N = NMAX;
    if (E > EMAX) E = EMAX;
    if (L > 3) L = 3;

    float* x = (float*)d_out;

    // graph preprocessing (CSR + normalization), rebuilt every call
    k_init<<<(N + 255) / 256, 256>>>(N);
    k_edge_deg<<<(E + 255) / 256, 256>>>(erow, evals, E);
    k_dinv<<<(N + 255) / 256, 256>>>(N);
    int nb = (N + 4095) / 4096;
    k_scanA<<<nb, 1024>>>(N);
    k_scanB<<<1, 32>>>(nb);
    k_scanC<<<(N + 255) / 256, 256>>>(N, E);
    k_scatter<<<(E + 255) / 256, 256>>>(erow, ecol, evals, E);

    // weight repack + nf fp16 conversion
    int wtot = 1536 + L * 4096;
    k_pack_w<<<(wtot + 255) / 256, 256>>>(Win, Wc, L);
    int cnt4 = N * INDIM / 4;
    k_cvt_nf<<<(cnt4 + 255) / 256, 256>>>(nf, cnt4);

    // input projection: x = relu(nf @ Win + bin)  (writes x fp32 + g_xh fp16)
    int gblocks = (N + 63) / 64;
    k_mma<3, 0, 0><<<gblocks, 256>>>(0, bin, x, N);

    // layers (commuted): y = x @ Wc[l] (fp16) ; x += relu(A_hat_norm @ y + bc[l])
    int spmm_blocks = (N * 32 + 255) / 256;
    for (int l = 0; l < L; l++) {
        k_mma<8, 1, 1><<<gblocks, 256>>>(1536 + l * 4096, nullptr, nullptr, N);
        k_spmm_fused<<<spmm_blocks, 256>>>(x, bc + (size_t)l * ND, N);
    }
}

// round 6
// speedup vs baseline: 1.9999x; 1.0587x over previous
#include <cuda_runtime.h>
#include <cuda_fp16.h>
#include <math.h>

// Problem constants (validated against in_sizes at launch)
#define NMAX 100000
#define NPAD 100128           // NMAX rounded up past 128-row tile
#define EMAX 3200000
#define ND   128
#define INDIM 48

// ---------------- scratch (device globals; no allocation allowed) ----------------
__device__ __align__(16) __half g_y[(size_t)NPAD * ND];    // x @ W (fp16), gathered by SpMM
__device__ __align__(16) __half g_xh[(size_t)NPAD * ND];   // fp16 copy of x (GEMM A operand)
__device__ __align__(16) __half g_nfh[(size_t)NPAD * INDIM]; // fp16 copy of node_features
__device__ __align__(16) uint2  g_wpack[1536 + 3 * 4096];  // W in mma-B-fragment order
__device__ float g_deg[NMAX];
__device__ float g_dinv[NMAX];
__device__ int   g_rowptr[NMAX + 1];
__device__ int   g_fill[NMAX];
__device__ __align__(8) int2 g_ecw[EMAX];   // CSR: (col, weight bits) interleaved
__device__ int   g_bsum[64];

// ---------------- small helpers ----------------
__device__ __forceinline__ void fma4(float4& d, float a, const float4& w) {
    d.x += a * w.x; d.y += a * w.y; d.z += a * w.z; d.w += a * w.w;
}
__device__ __forceinline__ float4 h4_to_f4(uint2 u) {
    __half2 a = *(__half2*)&u.x;
    __half2 b = *(__half2*)&u.y;
    float2 fa = __half22float2(a);
    float2 fb = __half22float2(b);
    return make_float4(fa.x, fa.y, fb.x, fb.y);
}
__device__ __forceinline__ unsigned pack_h2(float a, float b) {
    __half2 h = __floats2half2_rn(a, b);
    return *(unsigned*)&h;
}
__device__ __forceinline__ void mma16816(float4& c, unsigned a0, unsigned a1, unsigned a2,
                                         unsigned a3, unsigned b0, unsigned b1) {
    asm volatile(
        "mma.sync.aligned.m16n8k16.row.col.f32.f16.f16.f32 "
        "{%0,%1,%2,%3}, {%4,%5,%6,%7}, {%8,%9}, {%0,%1,%2,%3};\n"
        : "+f"(c.x), "+f"(c.y), "+f"(c.z), "+f"(c.w)
        : "r"(a0), "r"(a1), "r"(a2), "r"(a3), "r"(b0), "r"(b1));
}

// ---------------- graph preprocessing ----------------
__global__ void k_init(int n) {
    int i = blockIdx.x * blockDim.x + threadIdx.x;
    if (i < n) { g_deg[i] = 1.0f; g_fill[i] = 0; }   // 1.0f = self-loop value
}

__global__ void k_edge_deg(const int* __restrict__ row, const float* __restrict__ vals, int e) {
    int i = blockIdx.x * blockDim.x + threadIdx.x;
    if (i < e) {
        int r = row[i];
        atomicAdd(&g_deg[r], vals[i]);
        atomicAdd(&g_fill[r], 1);
    }
}

// scan over g_fill -> g_rowptr (tile-local), also computes dinv (deg is final here)
__global__ void k_scanA(int n) {
    __shared__ int s[1024];
    __shared__ int wsum[32];
    int t = threadIdx.x;
    int base = blockIdx.x * 4096;
    int v[4]; int sum = 0;
#pragma unroll
    for (int k = 0; k < 4; k++) {
        int idx = base + t * 4 + k;
        v[k] = (idx < n) ? g_fill[idx] : 0;
        if (idx < n) g_dinv[idx] = rsqrtf(fmaxf(g_deg[idx], 1.0f));
        sum += v[k];
    }
    // warp inclusive scan of per-thread sums
    int lane = t & 31, wid = t >> 5;
    int inc = sum;
#pragma unroll
    for (int off = 1; off < 32; off <<= 1) {
        int q = __shfl_up_sync(0xffffffff, inc, off);
        if (lane >= off) inc += q;
    }
    if (lane == 31) wsum[wid] = inc;
    __syncthreads();
    if (wid == 0) {
        int w = (lane < 32) ? wsum[lane] : 0;
#pragma unroll
        for (int off = 1; off < 32; off <<= 1) {
            int q = __shfl_up_sync(0xffffffff, w, off);
            if (lane >= off) w += q;
        }
        wsum[lane] = w;
    }
    __syncthreads();
    int excl = inc - sum + (wid > 0 ? wsum[wid - 1] : 0);
    if (t == 1023) g_bsum[blockIdx.x] = excl + sum;
    int run = excl;
#pragma unroll
    for (int k = 0; k < 4; k++) {
        int idx = base + t * 4 + k;
        if (idx < n) g_rowptr[idx] = run;
        run += v[k];
    }
    (void)s;
}

__global__ void k_scanB(int nb) {
    if (threadIdx.x == 0 && blockIdx.x == 0) {
        int acc = 0;
        for (int i = 0; i < nb; i++) { int t = g_bsum[i]; g_bsum[i] = acc; acc += t; }
    }
}

__global__ void k_scanC(int n, int e) {
    int i = blockIdx.x * blockDim.x + threadIdx.x;
    if (i < n) {
        g_rowptr[i] += g_bsum[i >> 12];
        g_fill[i] = 0;
    }
    if (i == 0) g_rowptr[n] = e;
}

__global__ void k_scatter(const int* __restrict__ row, const int* __restrict__ col,
                          const float* __restrict__ vals, int e) {
    int i = blockIdx.x * blockDim.x + threadIdx.x;
    if (i < e) {
        int r = row[i], c = col[i];
        int pos = g_rowptr[r] + atomicAdd(&g_fill[r], 1);
        float w = vals[i] * g_dinv[r] * g_dinv[c];
        g_ecw[pos] = make_int2(c, __float_as_int(w));
    }
}

// ---------------- weight repack + node_features fp16 conversion (fused) ----------------
// First wtot threads: pack W. Remaining cnt4 threads: convert nf (float4 -> 4 halfs).
// Pack: slot 0 Win (KC=3) [0,1536); slot l+1 Wc[l] at 1536 + l*4096.
// Fragment: index = kc*512 + nt*32 + lane; n = nt*8 + lane/4, k0 = kc*16 + (lane%4)*2
__global__ void k_prep(const float* __restrict__ Win, const float* __restrict__ Wc,
                       const float* __restrict__ nf, int L, int wtot, int cnt4) {
    int t = blockIdx.x * blockDim.x + threadIdx.x;
    if (t < wtot) {
        const float* W;
        int idx;
        if (t < 1536) { W = Win; idx = t; }
        else {
            int l = (t - 1536) >> 12;
            idx = (t - 1536) & 4095;
            W = Wc + (size_t)l * ND * ND;
        }
        int kc   = idx >> 9;
        int rest = idx & 511;
        int nt   = rest >> 5;
        int lane = rest & 31;
        int n  = nt * 8 + (lane >> 2);
        int k0 = kc * 16 + (lane & 3) * 2;
        uint2 p;
        p.x = pack_h2(W[(size_t)k0 * ND + n],       W[(size_t)(k0 + 1) * ND + n]);
        p.y = pack_h2(W[(size_t)(k0 + 8) * ND + n], W[(size_t)(k0 + 9) * ND + n]);
        g_wpack[t] = p;
    } else {
        int i = t - wtot;
        if (i < cnt4) {
            float4 v = ((const float4*)nf)[i];
            uint2 p;
            p.x = pack_h2(v.x, v.y);
            p.y = pack_h2(v.z, v.w);
            ((uint2*)g_nfh)[i] = p;
        }
    }
}

// ---------------- tensor-core GEMM ----------------
// Block: 64 rows x 128 cols, 256 threads (8 warps).
// Warp w: row-group rg = w/2 (rows [rg*16, rg*16+16)), col-half h = w%2 (cols [h*64, h*64+64)).
// MODE 0: out = relu(acc + bias) -> Xout fp32 AND g_xh fp16 (input projection)
// MODE 1: out = acc -> g_y fp16 (layer pre-aggregation)
template<int KC, int MODE, int ASEL>
__global__ void __launch_bounds__(256)
k_mma(int wofs, const float* __restrict__ bias, float* __restrict__ Xout, int n) {
    const int AS = KC * 16;
    const __half* A = (ASEL == 0) ? g_nfh : g_xh;
    int tid = threadIdx.x;
    int warp = tid >> 5, lane = tid & 31;
    int rg = warp >> 1, h = warp & 1;
    int g = lane >> 2, tq = lane & 3;
    int row0 = blockIdx.x * 64 + rg * 16;

    float4 acc[8];
#pragma unroll
    for (int nt = 0; nt < 8; nt++) acc[nt] = make_float4(0.f, 0.f, 0.f, 0.f);

    const __half* ar0 = A + (size_t)(row0 + g) * AS;
    const __half* ar8 = A + (size_t)(row0 + g + 8) * AS;
    const uint2* wp = g_wpack + wofs + h * 256 + lane;

#pragma unroll
    for (int kc = 0; kc < KC; kc++) {
        int k0 = kc * 16 + tq * 2;
        unsigned a0 = *(const unsigned*)(ar0 + k0);
        unsigned a1 = *(const unsigned*)(ar8 + k0);
        unsigned a2 = *(const unsigned*)(ar0 + k0 + 8);
        unsigned a3 = *(const unsigned*)(ar8 + k0 + 8);
        const uint2* w = wp + kc * 512;
#pragma unroll
        for (int nt = 0; nt < 8; nt++) {
            uint2 b = __ldg(&w[nt * 32]);
            mma16816(acc[nt], a0, a1, a2, a3, b.x, b.y);
        }
    }

    int r0 = row0 + g;
    int r1 = row0 + g + 8;
    bool ok0 = r0 < n, ok1 = r1 < n;
    int colb = h * 64 + tq * 2;

    if (MODE == 1) {
        __half* y0 = g_y + (size_t)r0 * ND + colb;
        __half* y1 = g_y + (size_t)r1 * ND + colb;
#pragma unroll
        for (int nt = 0; nt < 8; nt++) {
            unsigned h01 = pack_h2(acc[nt].x, acc[nt].y);
            unsigned h23 = pack_h2(acc[nt].z, acc[nt].w);
            if (ok0) *(unsigned*)(y0 + nt * 8) = h01;
            if (ok1) *(unsigned*)(y1 + nt * 8) = h23;
        }
    } else {
        __half* xh0 = g_xh + (size_t)r0 * ND + colb;
        __half* xh1 = g_xh + (size_t)r1 * ND + colb;
        float*  xo0 = Xout + (size_t)r0 * ND + colb;
        float*  xo1 = Xout + (size_t)r1 * ND + colb;
#pragma unroll
        for (int nt = 0; nt < 8; nt++) {
            float2 bb = __ldg(&((const float2*)bias)[h * 32 + nt * 4 + tq]);
            float v0 = fmaxf(acc[nt].x + bb.x, 0.f);
            float v1 = fmaxf(acc[nt].y + bb.y, 0.f);
            float v2 = fmaxf(acc[nt].z + bb.x, 0.f);
            float v3 = fmaxf(acc[nt].w + bb.y, 0.f);
            if (ok0) {
                *(float2*)(xo0 + nt * 8) = make_float2(v0, v1);
                *(unsigned*)(xh0 + nt * 8) = pack_h2(v0, v1);
            }
            if (ok1) {
                *(float2*)(xo1 + nt * 8) = make_float2(v2, v3);
                *(unsigned*)(xh1 + nt * 8) = pack_h2(v2, v3);
            }
        }
    }
}

// ---------------- SpMM (fp16 gather) + bias + ReLU + residual, fused ----------------
// x[w,:] += relu( sum_j ew[j]*y[col[j],:] + dinv[w]^2*y[w,:] + b ); also refresh g_xh
__global__ void k_spmm_fused(float* __restrict__ x, const float* __restrict__ b, int n) {
    int gt = blockIdx.x * blockDim.x + threadIdx.x;
    int w = gt >> 5;
    int lane = gt & 31;
    if (w >= n) return;
    const uint2* y2 = (const uint2*)g_y;        // 4 halfs per lane
    float di = g_dinv[w];
    float s = di * di;                          // self-loop weight
    float4 v = h4_to_f4(__ldg(&y2[(size_t)w * 32 + lane]));
    float4 acc = make_float4(s * v.x, s * v.y, s * v.z, s * v.w);
    int jb = g_rowptr[w], je = g_rowptr[w + 1];
    int j = jb;
    for (; j + 8 <= je; j += 8) {
        int2 e[8];
        uint2 u[8];
#pragma unroll
        for (int q = 0; q < 8; q++) e[q] = __ldg(&g_ecw[j + q]);
#pragma unroll
        for (int q = 0; q < 8; q++) u[q] = __ldg(&y2[(size_t)e[q].x * 32 + lane]);
#pragma unroll
        for (int q = 0; q < 8; q++) fma4(acc, __int_as_float(e[q].y), h4_to_f4(u[q]));
    }
    for (; j < je; j++) {
        int2 e = __ldg(&g_ecw[j]);
        fma4(acc, __int_as_float(e.y), h4_to_f4(__ldg(&y2[(size_t)e.x * 32 + lane])));
    }
    float4 bb = __ldg(&((const float4*)b)[lane]);
    float4* x4 = (float4*)x;
    float4 xv = x4[(size_t)w * 32 + lane];
    xv.x += fmaxf(acc.x + bb.x, 0.f);
    xv.y += fmaxf(acc.y + bb.y, 0.f);
    xv.z += fmaxf(acc.z + bb.z, 0.f);
    xv.w += fmaxf(acc.w + bb.w, 0.f);
    x4[(size_t)w * 32 + lane] = xv;
    uint2 p;
    p.x = pack_h2(xv.x, xv.y);
    p.y = pack_h2(xv.z, xv.w);
    ((uint2*)g_xh)[(size_t)w * 32 + lane] = p;
}

// ---------------- launch ----------------
extern "C" void kernel_launch(void* const* d_in, const int* in_sizes, int n_in,
                              void* d_out, int out_size) {
    const float* nf    = (const float*)d_in[0];   // [N,48]
    const int*   erow  = (const int*)d_in[1];     // [E]
    const int*   ecol  = (const int*)d_in[2];     // [E]
    const float* evals = (const float*)d_in[3];   // [E]
    const float* Win   = (const float*)d_in[4];   // [48,128]
    const float* bin   = (const float*)d_in[5];   // [128]
    const float* Wc    = (const float*)d_in[6];   // [L,128,128]
    const float* bc    = (const float*)d_in[7];   // [L,128]

    int N = in_sizes[0] / INDIM;
    int E = in_sizes[1];
    int L = in_sizes[6] / (ND * ND);
    if (N > NMAX) N = NMAX;
    if (E > EMAX) E = EMAX;
    if (L > 3) L = 3;

    float* x = (float*)d_out;

    // graph preprocessing (CSR + normalization), rebuilt every call
    k_init<<<(N + 255) / 256, 256>>>(N);
    k_edge_deg<<<(E + 255) / 256, 256>>>(erow, evals, E);
    int nb = (N + 4095) / 4096;
    k_scanA<<<nb, 1024>>>(N);                 // also computes dinv
    k_scanB<<<1, 32>>>(nb);
    k_scanC<<<(N + 255) / 256, 256>>>(N, E);
    k_scatter<<<(E + 255) / 256, 256>>>(erow, ecol, evals, E);

    // weight repack + nf fp16 conversion (one launch)
    int wtot = 1536 + L * 4096;
    int cnt4 = N * INDIM / 4;
    k_prep<<<(wtot + cnt4 + 255) / 256, 256>>>(Win, Wc, nf, L, wtot, cnt4);

    // input projection: x = relu(nf @ Win + bin)  (writes x fp32 + g_xh fp16)
    int gblocks = (N + 63) / 64;
    k_mma<3, 0, 0><<<gblocks, 256>>>(0, bin, x, N);

    // layers (commuted): y = x @ Wc[l] (fp16) ; x += relu(A_hat_norm @ y + bc[l])
    int spmm_blocks = (N * 32 + 255) / 256;
    for (int l = 0; l < L; l++) {
        k_mma<8, 1, 1><<<gblocks, 256>>>(1536 + l * 4096, nullptr, nullptr, N);
        k_spmm_fused<<<spmm_blocks, 256>>>(x, bc + (size_t)l * ND, N);
    }
}